// round 4
// baseline (speedup 1.0000x reference)
#include <cuda_runtime.h>
#include <cuda_bf16.h>

#define ULL unsigned long long

__device__ __forceinline__ ULL add2(ULL a, ULL b) {
    ULL r; asm("add.rn.f32x2 %0, %1, %2;" : "=l"(r) : "l"(a), "l"(b)); return r;
}
__device__ __forceinline__ void unpk2(ULL v, float& lo, float& hi) {
    asm("mov.b64 {%0, %1}, %2;" : "=f"(lo), "=f"(hi) : "l"(v));
}
__device__ __forceinline__ void cpasync16(void* sptr, const void* gptr) {
    unsigned sa = (unsigned)__cvta_generic_to_shared(sptr);
    asm volatile("cp.async.cg.shared.global [%0], [%1], 16;" :: "r"(sa), "l"(gptr) : "memory");
}
__device__ __forceinline__ void cp_commit() {
    asm volatile("cp.async.commit_group;" ::: "memory");
}
template <int N>
__device__ __forceinline__ void cp_wait() {
    asm volatile("cp.async.wait_group %0;" :: "n"(N) : "memory");
}

// Tile: 8 states x 512 cells per block of 256 threads, 3 blocks/SM.
// Thread (ts = tid>>6 in [0,4), tc = tid&63 in [0,64)):
//   states ts*2, ts*2+1; cells tc + j*64 for j in [0,8).
// Dims processed as 16 float4 "dim-quads" (dq), in 8 double-buffered chunks of 2 dqs.
// x is staged NEGATED so the inner loop is pure add2 + and (no xor, no movs).
__global__ __launch_bounds__(256, 3) void PlaceCells_kernel(
    const float* __restrict__ x, const float* __restrict__ pc,
    float* __restrict__ out, int nstates)
{
    __shared__ float4 cs4[2048];     // 2 bufs x (2 dq x 512 cells), swizzled: 32 KB
    __shared__ float4 xs4[128];      // 8 states x 16 dq (negated): 2 KB
    __shared__ float  wred[8][2];
    __shared__ float  wsum[8][2];

    const int tid = threadIdx.x;
    const int tc  = tid & 63;
    const int ts  = tid >> 6;
    const int bs  = blockIdx.x * 8;

    // ---- stage -x tile (8 states x 64 dims = 128 float4) ----
    if (tid < 128) {
        int s = tid >> 4, q = tid & 15;
        float4 v = reinterpret_cast<const float4*>(x)[(ULL)(bs + s) * 16 + q];
        xs4[tid] = make_float4(-v.x, -v.y, -v.z, -v.w);
    }

    const float4* pc4 = reinterpret_cast<const float4*>(pc);

    // ---- prologue: issue chunk 0 ----
    {
        #pragma unroll
        for (int r = 0; r < 4; r++) {
            int idx = r * 256 + tid;          // 0..1023
            int cell = idx >> 1, dql = idx & 1;
            cpasync16(&cs4[dql * 512 + (cell ^ (dql << 2))],
                      &pc4[cell * 16 + dql]);
        }
        cp_commit();
    }

    ULL acc[2][8];
    #pragma unroll
    for (int i = 0; i < 2; i++)
        #pragma unroll
        for (int j = 0; j < 8; j++) acc[i][j] = 0ULL;

    const ULL ABSM = 0x7FFFFFFF7FFFFFFFULL;

    const ulonglong2* csU = reinterpret_cast<const ulonglong2*>(cs4);
    const ulonglong2* xsU = reinterpret_cast<const ulonglong2*>(xs4);

    for (int k = 0; k < 8; k++) {
        __syncthreads();   // everyone done with buffer (k+1)&1 (chunk k-1); covers xs4 on k=0
        if (k < 7) {
            int buf = (k + 1) & 1;
            #pragma unroll
            for (int r = 0; r < 4; r++) {
                int idx = r * 256 + tid;
                int cell = idx >> 1, dql = idx & 1;
                cpasync16(&cs4[buf * 1024 + dql * 512 + (cell ^ (dql << 2))],
                          &pc4[cell * 16 + (k + 1) * 2 + dql]);
            }
            cp_commit();
            cp_wait<1>();
        } else {
            cp_wait<0>();
        }
        __syncthreads();   // chunk k visible to all

        const int buf = k & 1;
        #pragma unroll
        for (int dql = 0; dql < 2; dql++) {
            const int dq = k * 2 + dql;
            // negated x, packed: 4 dims per state (warp-uniform broadcast loads)
            ulonglong2 nx0 = xsU[(ts * 2 + 0) * 16 + dq];
            ulonglong2 nx1 = xsU[(ts * 2 + 1) * 16 + dq];
            #pragma unroll
            for (int j = 0; j < 8; j++) {
                const int c = tc + j * 64;
                ulonglong2 cv = csU[buf * 1024 + dql * 512 + (c ^ (dql << 2))];
                ULL a0 = add2(cv.x, nx0.x) & ABSM;   // |c - x| on 2 dims, state 0
                ULL a1 = add2(cv.y, nx0.y) & ABSM;
                acc[0][j] = add2(acc[0][j], a0);
                acc[0][j] = add2(acc[0][j], a1);
                ULL b0 = add2(cv.x, nx1.x) & ABSM;   // state 1
                ULL b1 = add2(cv.y, nx1.y) & ABSM;
                acc[1][j] = add2(acc[1][j], b0);
                acc[1][j] = add2(acc[1][j], b1);
            }
        }
    }

    // ---- finalize logits: u = -0.5 * l1^2 ----
    float u[2][8];
    #pragma unroll
    for (int i = 0; i < 2; i++)
        #pragma unroll
        for (int j = 0; j < 8; j++) {
            float lo, hi; unpk2(acc[i][j], lo, hi);
            float l1 = lo + hi;
            u[i][j] = -0.5f * l1 * l1;
        }

    const int lane = tid & 31;
    const int w    = tid >> 5;           // warps 2*ts, 2*ts+1 share a state group

    // ---- row max ----
    float lm[2];
    #pragma unroll
    for (int i = 0; i < 2; i++) {
        float m = u[i][0];
        #pragma unroll
        for (int j = 1; j < 8; j++) m = fmaxf(m, u[i][j]);
        #pragma unroll
        for (int off = 16; off > 0; off >>= 1)
            m = fmaxf(m, __shfl_xor_sync(0xffffffffu, m, off));
        lm[i] = m;
    }
    if (lane == 0) {
        #pragma unroll
        for (int i = 0; i < 2; i++) wred[w][i] = lm[i];
    }
    __syncthreads();
    float mrow[2];
    #pragma unroll
    for (int i = 0; i < 2; i++)
        mrow[i] = fmaxf(wred[2 * ts][i], wred[2 * ts + 1][i]);

    // ---- exp + row sum ----
    float ls[2];
    #pragma unroll
    for (int i = 0; i < 2; i++) {
        float s = 0.0f;
        #pragma unroll
        for (int j = 0; j < 8; j++) {
            float e = __expf(u[i][j] - mrow[i]);
            u[i][j] = e;
            s += e;
        }
        #pragma unroll
        for (int off = 16; off > 0; off >>= 1)
            s += __shfl_xor_sync(0xffffffffu, s, off);
        ls[i] = s;
    }
    if (lane == 0) {
        #pragma unroll
        for (int i = 0; i < 2; i++) wsum[w][i] = ls[i];
    }
    __syncthreads();

    #pragma unroll
    for (int i = 0; i < 2; i++) {
        float inv = 1.0f / (wsum[2 * ts][i] + wsum[2 * ts + 1][i]);
        const int srow = bs + ts * 2 + i;
        #pragma unroll
        for (int j = 0; j < 8; j++)
            out[(ULL)srow * 512 + tc + j * 64] = u[i][j] * inv;
    }
}

extern "C" void kernel_launch(void* const* d_in, const int* in_sizes, int n_in,
                              void* d_out, int out_size) {
    const float* a = (const float*)d_in[0];
    const float* b = (const float*)d_in[1];
    // x is the larger tensor (8192*64), placeCells is 512*64
    const float* x  = (in_sizes[0] >= in_sizes[1]) ? a : b;
    const float* pc = (in_sizes[0] >= in_sizes[1]) ? b : a;
    int xsz = (in_sizes[0] >= in_sizes[1]) ? in_sizes[0] : in_sizes[1];
    int nstates = xsz / 64;          // 8192
    int grid = nstates / 8;          // 1024 blocks

    PlaceCells_kernel<<<grid, 256>>>(x, pc, (float*)d_out, nstates);
}

// round 6
// speedup vs baseline: 1.0997x; 1.0997x over previous
#include <cuda_runtime.h>
#include <cuda_bf16.h>

#define ULL unsigned long long

__device__ __forceinline__ ULL add2(ULL a, ULL b) {
    ULL r; asm("add.rn.f32x2 %0, %1, %2;" : "=l"(r) : "l"(a), "l"(b)); return r;
}
__device__ __forceinline__ void unpk2(ULL v, float& lo, float& hi) {
    asm("mov.b64 {%0, %1}, %2;" : "=f"(lo), "=f"(hi) : "l"(v));
}
__device__ __forceinline__ void cpasync16(void* sptr, const void* gptr) {
    unsigned sa = (unsigned)__cvta_generic_to_shared(sptr);
    asm volatile("cp.async.cg.shared.global [%0], [%1], 16;" :: "r"(sa), "l"(gptr) : "memory");
}
__device__ __forceinline__ void cp_commit() {
    asm volatile("cp.async.commit_group;" ::: "memory");
}
template <int N>
__device__ __forceinline__ void cp_wait() {
    asm volatile("cp.async.wait_group %0;" :: "n"(N) : "memory");
}

// Tile: 16 states x 512 cells per block of 512 threads, 2 blocks/SM.
// Thread (sg = tid>>6 in [0,8), tc = tid&63 in [0,64)):
//   states sg*2, sg*2+1; cells tc + j*64 for j in [0,8).
// Dims: 16 float4 "dim-quads" (dq) in 4 double-buffered chunks of 4 dqs (16 dims).
// x staged NEGATED so the inner loop is pure add2 + and.
// Dynamic smem: cs4 = 2 bufs x (4 dq x 512 cells) float4 = 64 KB; xs4 = 4 KB.
__global__ __launch_bounds__(512, 2) void PlaceCells_kernel(
    const float* __restrict__ x, const float* __restrict__ pc,
    float* __restrict__ out, int nstates)
{
    extern __shared__ char smem[];
    float4* cs4 = reinterpret_cast<float4*>(smem);            // [2][2048]
    float4* xs4 = reinterpret_cast<float4*>(smem + 65536);    // [256] = 16 states x 16 dq

    __shared__ float wred[16][2];
    __shared__ float wsum[16][2];

    const int tid = threadIdx.x;
    const int tc  = tid & 63;
    const int sg  = tid >> 6;
    const int bs  = blockIdx.x * 16;

    // ---- stage -x tile (16 states x 64 dims = 256 float4) ----
    if (tid < 256) {
        int s = tid >> 4, q = tid & 15;
        float4 v = reinterpret_cast<const float4*>(x)[(ULL)(bs + s) * 16 + q];
        xs4[tid] = make_float4(-v.x, -v.y, -v.z, -v.w);
    }

    const float4* pc4 = reinterpret_cast<const float4*>(pc);

    // ---- prologue: issue chunk 0 (dims 0..15 = dq 0..3) ----
    #pragma unroll
    for (int r = 0; r < 4; r++) {
        int idx = r * 512 + tid;          // 0..2047
        int dql = idx >> 9, cell = idx & 511;
        cpasync16(&cs4[dql * 512 + cell], &pc4[cell * 16 + dql]);
    }
    cp_commit();

    ULL acc[2][8];
    #pragma unroll
    for (int i = 0; i < 2; i++)
        #pragma unroll
        for (int j = 0; j < 8; j++) acc[i][j] = 0ULL;

    const ULL ABSM = 0x7FFFFFFF7FFFFFFFULL;
    const ulonglong2* xsU = reinterpret_cast<const ulonglong2*>(xs4);

    for (int k = 0; k < 4; k++) {
        __syncthreads();   // buffer (k+1)&1 free (chunk k-1 consumed); covers xs4 on k=0
        if (k < 3) {
            int buf = (k + 1) & 1;
            #pragma unroll
            for (int r = 0; r < 4; r++) {
                int idx = r * 512 + tid;
                int dql = idx >> 9, cell = idx & 511;
                cpasync16(&cs4[buf * 2048 + dql * 512 + cell],
                          &pc4[cell * 16 + (k + 1) * 4 + dql]);
            }
            cp_commit();
            cp_wait<1>();
        } else {
            cp_wait<0>();
        }
        __syncthreads();   // chunk k visible to all

        const ulonglong2* csU =
            reinterpret_cast<const ulonglong2*>(cs4 + (k & 1) * 2048);
        #pragma unroll
        for (int dql = 0; dql < 4; dql++) {
            const int dq = k * 4 + dql;
            ulonglong2 nx0 = xsU[(sg * 2 + 0) * 16 + dq];   // warp-uniform broadcast
            ulonglong2 nx1 = xsU[(sg * 2 + 1) * 16 + dq];
            #pragma unroll
            for (int j = 0; j < 8; j++) {
                ulonglong2 cv = csU[dql * 512 + tc + j * 64];
                ULL a0 = add2(cv.x, nx0.x) & ABSM;   // |c - x| on 2 dims, state 0
                ULL a1 = add2(cv.y, nx0.y) & ABSM;
                acc[0][j] = add2(acc[0][j], a0);
                acc[0][j] = add2(acc[0][j], a1);
                ULL b0 = add2(cv.x, nx1.x) & ABSM;   // state 1
                ULL b1 = add2(cv.y, nx1.y) & ABSM;
                acc[1][j] = add2(acc[1][j], b0);
                acc[1][j] = add2(acc[1][j], b1);
            }
        }
    }

    // ---- finalize logits: u = -0.5 * l1^2 ----
    float u[2][8];
    #pragma unroll
    for (int i = 0; i < 2; i++)
        #pragma unroll
        for (int j = 0; j < 8; j++) {
            float lo, hi; unpk2(acc[i][j], lo, hi);
            float l1 = lo + hi;
            u[i][j] = -0.5f * l1 * l1;
        }

    const int lane = tid & 31;
    const int w    = tid >> 5;           // warps 2*sg, 2*sg+1 share a state group

    // ---- row max ----
    float lm[2];
    #pragma unroll
    for (int i = 0; i < 2; i++) {
        float m = u[i][0];
        #pragma unroll
        for (int j = 1; j < 8; j++) m = fmaxf(m, u[i][j]);
        #pragma unroll
        for (int off = 16; off > 0; off >>= 1)
            m = fmaxf(m, __shfl_xor_sync(0xffffffffu, m, off));
        lm[i] = m;
    }
    if (lane == 0) {
        #pragma unroll
        for (int i = 0; i < 2; i++) wred[w][i] = lm[i];
    }
    __syncthreads();
    float mrow[2];
    #pragma unroll
    for (int i = 0; i < 2; i++)
        mrow[i] = fmaxf(wred[2 * sg][i], wred[2 * sg + 1][i]);

    // ---- exp + row sum ----
    float ls[2];
    #pragma unroll
    for (int i = 0; i < 2; i++) {
        float s = 0.0f;
        #pragma unroll
        for (int j = 0; j < 8; j++) {
            float e = __expf(u[i][j] - mrow[i]);
            u[i][j] = e;
            s += e;
        }
        #pragma unroll
        for (int off = 16; off > 0; off >>= 1)
            s += __shfl_xor_sync(0xffffffffu, s, off);
        ls[i] = s;
    }
    if (lane == 0) {
        #pragma unroll
        for (int i = 0; i < 2; i++) wsum[w][i] = ls[i];
    }
    __syncthreads();

    #pragma unroll
    for (int i = 0; i < 2; i++) {
        float inv = 1.0f / (wsum[2 * sg][i] + wsum[2 * sg + 1][i]);
        const int srow = bs + sg * 2 + i;
        #pragma unroll
        for (int j = 0; j < 8; j++)
            out[(ULL)srow * 512 + tc + j * 64] = u[i][j] * inv;
    }
}

extern "C" void kernel_launch(void* const* d_in, const int* in_sizes, int n_in,
                              void* d_out, int out_size) {
    const float* a = (const float*)d_in[0];
    const float* b = (const float*)d_in[1];
    // x is the larger tensor (8192*64), placeCells is 512*64
    const float* x  = (in_sizes[0] >= in_sizes[1]) ? a : b;
    const float* pc = (in_sizes[0] >= in_sizes[1]) ? b : a;
    int xsz = (in_sizes[0] >= in_sizes[1]) ? in_sizes[0] : in_sizes[1];
    int nstates = xsz / 64;          // 8192
    int grid = nstates / 16;         // 512 blocks

    const int dyn_smem = 65536 + 4096;   // cs4 (64 KB) + xs4 (4 KB)
    static int attr_set = 0;
    if (!attr_set) {
        cudaFuncSetAttribute(PlaceCells_kernel,
                             cudaFuncAttributeMaxDynamicSharedMemorySize, dyn_smem);
        attr_set = 1;
    }
    PlaceCells_kernel<<<grid, 512, dyn_smem>>>(x, pc, (float*)d_out, nstates);
}

// round 7
// speedup vs baseline: 1.3704x; 1.2461x over previous
#include <cuda_runtime.h>
#include <cuda_bf16.h>

#define ULL unsigned long long

__device__ __forceinline__ ULL add2(ULL a, ULL b) {
    ULL r; asm("add.rn.f32x2 %0, %1, %2;" : "=l"(r) : "l"(a), "l"(b)); return r;
}
__device__ __forceinline__ void unpk2(ULL v, float& lo, float& hi) {
    asm("mov.b64 {%0, %1}, %2;" : "=f"(lo), "=f"(hi) : "l"(v));
}

// Persistent-ish design: grid = #SMs, 1 block/SM (smem-bound).
// Block stages the ENTIRE codebook (512 cells x 64 dims = 128 KB) in smem ONCE.
// Then loops over 32-state tiles (256 tiles total, strided by gridDim).
// Mainloop has ZERO barriers / cp.async waits: pure LDS + FADD2 + LOP3.
// 512 threads = 8 groups (sg) of 64 (tc); group handles 4 states, thread handles
// cells tc + j*64, j in [0,8). Each cv LDS.128 (4 dims of one cell) feeds 4 states.
// x staged NEGATED so inner loop is add2 + and only.
__global__ __launch_bounds__(512, 1) void PlaceCells_kernel(
    const float* __restrict__ x, const float* __restrict__ pc,
    float* __restrict__ out, int nblocks)
{
    extern __shared__ char smem[];
    float4* cs4 = reinterpret_cast<float4*>(smem);             // [16 dq][512 cells] = 128 KB
    float4* xs4 = reinterpret_cast<float4*>(smem + 131072);    // [32 states][16 dq] = 8 KB

    __shared__ float wred[16][4];
    __shared__ float wsum[16][4];

    const int tid  = threadIdx.x;
    const int tc   = tid & 63;
    const int sg   = tid >> 6;        // 0..7
    const int lane = tid & 31;
    const int w    = tid >> 5;        // 0..15; warps 2*sg, 2*sg+1 form a group

    // ---- stage full codebook once: cs4[dq*512 + cell] ----
    const float4* pc4 = reinterpret_cast<const float4*>(pc);
    #pragma unroll
    for (int i = 0; i < 16; i++)
        cs4[i * 512 + tid] = pc4[tid * 16 + i];     // smem stores conflict-free

    const float4* x4 = reinterpret_cast<const float4*>(x);
    const ulonglong2* csU = reinterpret_cast<const ulonglong2*>(cs4);
    const ulonglong2* xsU = reinterpret_cast<const ulonglong2*>(xs4);
    const ULL ABSM = 0x7FFFFFFF7FFFFFFFULL;

    for (int tile = blockIdx.x; tile < 256; tile += nblocks) {
        const int bs = tile * 32;

        __syncthreads();   // xs4/wred/wsum free from previous tile
        // ---- stage -x for this tile: 32 states x 16 dq ----
        {
            int s = tid >> 4, q = tid & 15;
            float4 v = x4[(ULL)(bs + s) * 16 + q];
            xs4[tid] = make_float4(-v.x, -v.y, -v.z, -v.w);
        }
        __syncthreads();   // x visible (and codebook, on first tile)

        // ---- barrier-free mainloop ----
        ULL acc[4][8];
        #pragma unroll
        for (int i = 0; i < 4; i++)
            #pragma unroll
            for (int j = 0; j < 8; j++) acc[i][j] = 0ULL;

        #pragma unroll 2
        for (int dq = 0; dq < 16; dq++) {
            ulonglong2 nx[4];
            #pragma unroll
            for (int i = 0; i < 4; i++)
                nx[i] = xsU[(sg * 4 + i) * 16 + dq];   // warp-uniform broadcast
            #pragma unroll
            for (int j = 0; j < 8; j++) {
                ulonglong2 cv = csU[dq * 512 + tc + j * 64];  // conflict-free
                #pragma unroll
                for (int i = 0; i < 4; i++) {
                    ULL d0 = add2(cv.x, nx[i].x) & ABSM;  // |c - x| on 2 dims
                    ULL d1 = add2(cv.y, nx[i].y) & ABSM;
                    acc[i][j] = add2(acc[i][j], d0);
                    acc[i][j] = add2(acc[i][j], d1);
                }
            }
        }

        // ---- logits u = -0.5 * l1^2 ----
        float u[4][8];
        #pragma unroll
        for (int i = 0; i < 4; i++)
            #pragma unroll
            for (int j = 0; j < 8; j++) {
                float lo, hi; unpk2(acc[i][j], lo, hi);
                float l1 = lo + hi;
                u[i][j] = -0.5f * l1 * l1;
            }

        // ---- row max (per 64-thread group = 2 warps) ----
        #pragma unroll
        for (int i = 0; i < 4; i++) {
            float m = u[i][0];
            #pragma unroll
            for (int j = 1; j < 8; j++) m = fmaxf(m, u[i][j]);
            #pragma unroll
            for (int off = 16; off > 0; off >>= 1)
                m = fmaxf(m, __shfl_xor_sync(0xffffffffu, m, off));
            if (lane == 0) wred[w][i] = m;
        }
        __syncthreads();
        float mrow[4];
        #pragma unroll
        for (int i = 0; i < 4; i++)
            mrow[i] = fmaxf(wred[2 * sg][i], wred[2 * sg + 1][i]);

        // ---- exp + row sum ----
        #pragma unroll
        for (int i = 0; i < 4; i++) {
            float s = 0.0f;
            #pragma unroll
            for (int j = 0; j < 8; j++) {
                float e = __expf(u[i][j] - mrow[i]);
                u[i][j] = e;
                s += e;
            }
            #pragma unroll
            for (int off = 16; off > 0; off >>= 1)
                s += __shfl_xor_sync(0xffffffffu, s, off);
            if (lane == 0) wsum[w][i] = s;
        }
        __syncthreads();

        #pragma unroll
        for (int i = 0; i < 4; i++) {
            float inv = 1.0f / (wsum[2 * sg][i] + wsum[2 * sg + 1][i]);
            const int srow = bs + sg * 4 + i;
            #pragma unroll
            for (int j = 0; j < 8; j++)
                out[(ULL)srow * 512 + tc + j * 64] = u[i][j] * inv;
        }
    }
}

extern "C" void kernel_launch(void* const* d_in, const int* in_sizes, int n_in,
                              void* d_out, int out_size) {
    const float* a = (const float*)d_in[0];
    const float* b = (const float*)d_in[1];
    // x is the larger tensor (8192*64), placeCells is 512*64
    const float* x  = (in_sizes[0] >= in_sizes[1]) ? a : b;
    const float* pc = (in_sizes[0] >= in_sizes[1]) ? b : a;

    const int dyn_smem = 131072 + 8192;   // codebook 128 KB + x tile 8 KB

    static int nsm = 0;
    if (!nsm) {
        cudaDeviceGetAttribute(&nsm, cudaDevAttrMultiProcessorCount, 0);
        if (nsm <= 0) nsm = 148;
        cudaFuncSetAttribute(PlaceCells_kernel,
                             cudaFuncAttributeMaxDynamicSharedMemorySize, dyn_smem);
    }
    PlaceCells_kernel<<<nsm, 512, dyn_smem>>>(x, pc, (float*)d_out, nsm);
}